// round 12
// baseline (speedup 1.0000x reference)
#include <cuda_runtime.h>
#include <cuda_fp16.h>
#include <cstdint>

// LCA layer via mma.sync fp16 GEMMs, entirely against W~ = fp16(W):
//   b = fp16(x)@W~ ;  u1 = 0.1*b
//   9x: a = relu(u-0.1); t1 = a@W~^T; u = 0.9u + 0.1*(b - t1@W~ + a*diagG~)
//   out = fp16(relu(u-0.1)) @ W~^T
// Single fp16 term per operand (20 GEMM-units). The N=1024 GEMMs (t1, out)
// use a 64x128-tile kernel (1024 CTAs -> 7 waves, 1.2% tail) instead of the
// 128x256-tile kernel (256 CTAs -> 2 waves, 15.6% tail). 1 CTA/SM enforced
// via smem padding so the tail stays at wave granularity 7/6.92.

static constexpr int NROWS  = 8192;
static constexpr int DMODEL = 1024;
static constexpr int DLCA   = 4096;
static constexpr float LAMBDA = 0.1f;
static constexpr float BETA   = 0.1f;
static constexpr float ONE_MB = 0.9f;

// ---------------------------------------------------------------- scratch
__device__ float g_b [(size_t)NROWS * DLCA];
__device__ float g_u [(size_t)NROWS * DLCA];
__device__ __half g_ahi[(size_t)NROWS * DLCA];
__device__ __half g_t1hi[(size_t)NROWS * DMODEL];
__device__ __half g_xhi[(size_t)NROWS * DMODEL];
__device__ __half g_Whi[(size_t)DMODEL * DLCA];   // [d, n] row-major
__device__ __half g_Wthi[(size_t)DLCA * DMODEL];  // [n, d] row-major
__device__ float g_diagG[DLCA];

// ---------------------------------------------------------------- asm helpers
__device__ __forceinline__ uint32_t smem_u32(const void* p) {
    uint32_t a;
    asm("{ .reg .u64 t; cvta.to.shared.u64 t, %1; cvt.u32.u64 %0, t; }" : "=r"(a) : "l"(p));
    return a;
}
__device__ __forceinline__ void cp16(uint32_t dst, const void* src) {
    asm volatile("cp.async.cg.shared.global [%0], [%1], 16;" :: "r"(dst), "l"(src));
}
__device__ __forceinline__ void cp_commit() {
    asm volatile("cp.async.commit_group;" ::: "memory");
}
template <int N>
__device__ __forceinline__ void cp_wait() {
    asm volatile("cp.async.wait_group %0;" :: "n"(N) : "memory");
}
__device__ __forceinline__ void ldsm4(uint32_t* r, uint32_t addr) {
    asm volatile("ldmatrix.sync.aligned.m8n8.x4.shared.b16 {%0,%1,%2,%3}, [%4];"
                 : "=r"(r[0]), "=r"(r[1]), "=r"(r[2]), "=r"(r[3]) : "r"(addr));
}
__device__ __forceinline__ void mma_f16(float* c, const uint32_t* a,
                                        uint32_t b0, uint32_t b1) {
    asm volatile(
        "mma.sync.aligned.m16n8k16.row.col.f32.f16.f16.f32 "
        "{%0,%1,%2,%3}, {%4,%5,%6,%7}, {%8,%9}, {%0,%1,%2,%3};"
        : "+f"(c[0]), "+f"(c[1]), "+f"(c[2]), "+f"(c[3])
        : "r"(a[0]), "r"(a[1]), "r"(a[2]), "r"(a[3]), "r"(b0), "r"(b1));
}

// ---------------------------------------------------------------- prep kernels
__global__ void zero_diag_kernel() {
    int i = blockIdx.x * blockDim.x + threadIdx.x;
    if (i < DLCA) g_diagG[i] = 0.f;
}
__global__ void diag_kernel() {
    int n  = blockIdx.x * 512 + threadIdx.x;
    int d0 = blockIdx.y * 64;
    float s = 0.f;
    #pragma unroll 8
    for (int d = d0; d < d0 + 64; ++d) {
        float w = __half2float(g_Whi[(size_t)d * DLCA + n]);
        s = fmaf(w, w, s);
    }
    atomicAdd(&g_diagG[n], s);
}

__global__ void half_kernel(const float* __restrict__ src, __half* __restrict__ hi) {
    size_t i = ((size_t)blockIdx.x * blockDim.x + threadIdx.x) * 4;
    float4 v = *reinterpret_cast<const float4*>(src + i);
    __half2 hp[2];
    hp[0] = __halves2half2(__float2half_rn(v.x), __float2half_rn(v.y));
    hp[1] = __halves2half2(__float2half_rn(v.z), __float2half_rn(v.w));
    *reinterpret_cast<uint2*>(hi + i) = *reinterpret_cast<const uint2*>(hp);
}

__global__ void transpose_kernel(const float* __restrict__ W) {
    __shared__ float tile[32][33];
    int bx = blockIdx.x * 32;   // n
    int by = blockIdx.y * 32;   // d
    for (int i = threadIdx.y; i < 32; i += 8)
        tile[i][threadIdx.x] = W[(size_t)(by + i) * DLCA + bx + threadIdx.x];
    __syncthreads();
    for (int i = threadIdx.y; i < 32; i += 8) {
        int n = bx + i;
        int d = by + threadIdx.x;
        g_Wthi[(size_t)n * DMODEL + d] = __float2half_rn(tile[threadIdx.x][i]);
    }
}

// ---------------------------------------------------------------- big GEMM
// C tile 128(M) x 256(N); used for b-init (EPI 0) and LCA update (EPI 2).
// 512 threads, 16 warps 4Mx4N, warp 32x64. BK=64, 144B smem pitch, 3 stages.
static constexpr int ROWB   = 144;
static constexpr int A_TILE = 128 * ROWB;    // 18432
static constexpr int B_TILE = 256 * ROWB;    // 36864
static constexpr int STAGE_BYTES = A_TILE + B_TILE;        // 55296
static constexpr int SMEM_BIG    = 3 * STAGE_BYTES;        // 165888

__device__ __forceinline__ void stage_load_big(uint32_t sb,
        const __half* __restrict__ Ah, const __half* __restrict__ Bh,
        int rowBase, int colBase, int k0, int K, int tid) {
    #pragma unroll
    for (int i = 0; i < 2; ++i) {
        int idx = tid + i * 512;
        int r = idx >> 3, cc = idx & 7;
        uint32_t off = (uint32_t)(r * ROWB + cc * 16);
        cp16(sb + off, Ah + (size_t)(rowBase + r) * K + k0 + cc * 8);
    }
    #pragma unroll
    for (int i = 0; i < 4; ++i) {
        int idx = tid + i * 512;
        int r = idx >> 3, cc = idx & 7;
        uint32_t off = (uint32_t)(r * ROWB + cc * 16);
        cp16(sb + A_TILE + off, Bh + (size_t)(colBase + r) * K + k0 + cc * 8);
    }
}

template <int EPI>    // 0 = b-init, 2 = LCA update
__global__ void __launch_bounds__(512, 1)
lca_gemm_big(const __half* __restrict__ Ah, const __half* __restrict__ Bh,
             int K) {
    extern __shared__ __align__(256) char smem[];
    const uint32_t sbase = smem_u32(smem);
    const int tid = threadIdx.x;
    const int wid = tid >> 5;
    const int lid = tid & 31;
    const int warpM = wid >> 2;
    const int warpN = wid & 3;
    const int rowBase = blockIdx.y * 128;
    const int colBase = blockIdx.x * 256;
    const int KT = K >> 6;

    float acc[2][8][4];
    #pragma unroll
    for (int mi = 0; mi < 2; ++mi)
        #pragma unroll
        for (int ni = 0; ni < 8; ++ni)
            #pragma unroll
            for (int q = 0; q < 4; ++q) acc[mi][ni][q] = 0.f;

    stage_load_big(sbase, Ah, Bh, rowBase, colBase, 0, K, tid);
    cp_commit();
    stage_load_big(sbase + STAGE_BYTES, Ah, Bh, rowBase, colBase, 64, K, tid);
    cp_commit();

    const uint32_t lrow = (uint32_t)(lid & 15);
    const uint32_t lcol = (uint32_t)((lid >> 4) * 16);

    int sidx = 0;
    for (int kt = 0; kt < KT; ++kt) {
        cp_wait<1>();
        __syncthreads();

        if (kt + 2 < KT)
            stage_load_big(sbase + ((sidx + 2) % 3) * STAGE_BYTES,
                           Ah, Bh, rowBase, colBase, (kt + 2) * 64, K, tid);
        cp_commit();

        const uint32_t sb = sbase + sidx * STAGE_BYTES;
        const uint32_t aBase = sb + (uint32_t)(warpM * 32) * ROWB;
        const uint32_t bBase = sb + A_TILE + (uint32_t)(warpN * 64) * ROWB;

        #pragma unroll
        for (int ks = 0; ks < 4; ++ks) {
            const uint32_t kb = (uint32_t)(ks * 32) + lcol;
            uint32_t ah[2][4], bf[4][4];
            #pragma unroll
            for (int mi = 0; mi < 2; ++mi)
                ldsm4(ah[mi], aBase + (uint32_t)(mi * 16 + lrow) * ROWB + kb);
            #pragma unroll
            for (int nj = 0; nj < 4; ++nj)
                ldsm4(bf[nj], bBase + (uint32_t)(nj * 16 + lrow) * ROWB + kb);

            #pragma unroll
            for (int mi = 0; mi < 2; ++mi)
                #pragma unroll
                for (int ni = 0; ni < 8; ++ni) {
                    const int nj = ni >> 1, nr = ni & 1;
                    mma_f16(acc[mi][ni], ah[mi], bf[nj][nr], bf[nj][nr + 2]);
                }
        }
        __syncthreads();
        sidx = (sidx + 1) % 3;
    }

    const int qrow = lid >> 2;
    const int qcol = (lid & 3) * 2;

    #pragma unroll
    for (int mi = 0; mi < 2; ++mi) {
        #pragma unroll
        for (int ni = 0; ni < 8; ++ni) {
            const int r0 = rowBase + warpM * 32 + mi * 16 + qrow;
            const int c  = colBase + warpN * 64 + ni * 8 + qcol;
            #pragma unroll
            for (int h = 0; h < 2; ++h) {
                const int r = r0 + h * 8;
                const size_t base = (size_t)r * DLCA + c;
                const float v0 = acc[mi][ni][2*h], v1 = acc[mi][ni][2*h + 1];
                if (EPI == 0) {
                    float u0 = BETA * v0, u1 = BETA * v1;
                    *reinterpret_cast<float2*>(g_b + base) = make_float2(v0, v1);
                    *reinterpret_cast<float2*>(g_u + base) = make_float2(u0, u1);
                    float a0 = fmaxf(u0 - LAMBDA, 0.f), a1 = fmaxf(u1 - LAMBDA, 0.f);
                    *reinterpret_cast<__half2*>(g_ahi + base) =
                        __halves2half2(__float2half_rn(a0), __float2half_rn(a1));
                } else {
                    float2 uo = *reinterpret_cast<const float2*>(g_u + base);
                    float2 bv = *reinterpret_cast<const float2*>(g_b + base);
                    float2 dg = *reinterpret_cast<const float2*>(g_diagG + c);
                    float ao0 = fmaxf(uo.x - LAMBDA, 0.f), ao1 = fmaxf(uo.y - LAMBDA, 0.f);
                    float u0 = ONE_MB * uo.x + BETA * (bv.x - v0 + ao0 * dg.x);
                    float u1 = ONE_MB * uo.y + BETA * (bv.y - v1 + ao1 * dg.y);
                    *reinterpret_cast<float2*>(g_u + base) = make_float2(u0, u1);
                    float a0 = fmaxf(u0 - LAMBDA, 0.f), a1 = fmaxf(u1 - LAMBDA, 0.f);
                    *reinterpret_cast<__half2*>(g_ahi + base) =
                        __halves2half2(__float2half_rn(a0), __float2half_rn(a1));
                }
            }
        }
    }
}

// ---------------------------------------------------------------- small GEMM
// C tile 64(M) x 128(N); used for t1 (EPI 1) and out (EPI 3): N=1024 ->
// 1024 CTAs -> 7 waves over 148 SMs (1.2% tail vs 15.6% at 256 CTAs).
// 256 threads, 8 warps 2Mx4N, warp 32x32. Same BK=64 / 144B pitch / 3 stages.
static constexpr int AS_TILE = 64 * ROWB;                      //  9216
static constexpr int BS_TILE = 128 * ROWB;                     // 18432
static constexpr int SSTAGE_BYTES = AS_TILE + BS_TILE;         // 27648
static constexpr int SMEM_SMALL   = 118784;  // pad past 114KB -> 1 CTA/SM

__device__ __forceinline__ void stage_load_small(uint32_t sb,
        const __half* __restrict__ Ah, const __half* __restrict__ Bh,
        int rowBase, int colBase, int k0, int K, int tid) {
    #pragma unroll
    for (int i = 0; i < 2; ++i) {
        int idx = tid + i * 256;            // 512 chunks: 64 rows x 8
        int r = idx >> 3, cc = idx & 7;
        uint32_t off = (uint32_t)(r * ROWB + cc * 16);
        cp16(sb + off, Ah + (size_t)(rowBase + r) * K + k0 + cc * 8);
    }
    #pragma unroll
    for (int i = 0; i < 4; ++i) {
        int idx = tid + i * 256;            // 1024 chunks: 128 rows x 8
        int r = idx >> 3, cc = idx & 7;
        uint32_t off = (uint32_t)(r * ROWB + cc * 16);
        cp16(sb + AS_TILE + off, Bh + (size_t)(colBase + r) * K + k0 + cc * 8);
    }
}

template <int EPI>    // 1 = t1 fp16, 3 = out fp32
__global__ void __launch_bounds__(256, 1)
lca_gemm_small(const __half* __restrict__ Ah, const __half* __restrict__ Bh,
               int K, float* __restrict__ outp) {
    extern __shared__ __align__(256) char smem[];
    const uint32_t sbase = smem_u32(smem);
    const int tid = threadIdx.x;
    const int wid = tid >> 5;
    const int lid = tid & 31;
    const int warpM = wid >> 2;          // 0..1 (m offset 32)
    const int warpN = wid & 3;           // 0..3 (n offset 32)
    const int rowBase = blockIdx.y * 64;
    const int colBase = blockIdx.x * 128;
    const int KT = K >> 6;

    float acc[2][4][4];
    #pragma unroll
    for (int mi = 0; mi < 2; ++mi)
        #pragma unroll
        for (int ni = 0; ni < 4; ++ni)
            #pragma unroll
            for (int q = 0; q < 4; ++q) acc[mi][ni][q] = 0.f;

    stage_load_small(sbase, Ah, Bh, rowBase, colBase, 0, K, tid);
    cp_commit();
    stage_load_small(sbase + SSTAGE_BYTES, Ah, Bh, rowBase, colBase, 64, K, tid);
    cp_commit();

    const uint32_t lrow = (uint32_t)(lid & 15);
    const uint32_t lcol = (uint32_t)((lid >> 4) * 16);

    int sidx = 0;
    for (int kt = 0; kt < KT; ++kt) {
        cp_wait<1>();
        __syncthreads();

        if (kt + 2 < KT)
            stage_load_small(sbase + ((sidx + 2) % 3) * SSTAGE_BYTES,
                             Ah, Bh, rowBase, colBase, (kt + 2) * 64, K, tid);
        cp_commit();

        const uint32_t sb = sbase + sidx * SSTAGE_BYTES;
        const uint32_t aBase = sb + (uint32_t)(warpM * 32) * ROWB;
        const uint32_t bBase = sb + AS_TILE + (uint32_t)(warpN * 32) * ROWB;

        #pragma unroll
        for (int ks = 0; ks < 4; ++ks) {
            const uint32_t kb = (uint32_t)(ks * 32) + lcol;
            uint32_t ah[2][4], bf[2][4];
            #pragma unroll
            for (int mi = 0; mi < 2; ++mi)
                ldsm4(ah[mi], aBase + (uint32_t)(mi * 16 + lrow) * ROWB + kb);
            #pragma unroll
            for (int nj = 0; nj < 2; ++nj)
                ldsm4(bf[nj], bBase + (uint32_t)(nj * 16 + lrow) * ROWB + kb);

            #pragma unroll
            for (int mi = 0; mi < 2; ++mi)
                #pragma unroll
                for (int ni = 0; ni < 4; ++ni) {
                    const int nj = ni >> 1, nr = ni & 1;
                    mma_f16(acc[mi][ni], ah[mi], bf[nj][nr], bf[nj][nr + 2]);
                }
        }
        __syncthreads();
        sidx = (sidx + 1) % 3;
    }

    const int qrow = lid >> 2;
    const int qcol = (lid & 3) * 2;

    #pragma unroll
    for (int mi = 0; mi < 2; ++mi) {
        #pragma unroll
        for (int ni = 0; ni < 4; ++ni) {
            const int r0 = rowBase + warpM * 32 + mi * 16 + qrow;
            const int c  = colBase + warpN * 32 + ni * 8 + qcol;
            #pragma unroll
            for (int h = 0; h < 2; ++h) {
                const int r = r0 + h * 8;
                const size_t base = (size_t)r * DMODEL + c;
                const float v0 = acc[mi][ni][2*h], v1 = acc[mi][ni][2*h + 1];
                if (EPI == 1) {
                    *reinterpret_cast<__half2*>(g_t1hi + base) =
                        __halves2half2(__float2half_rn(v0), __float2half_rn(v1));
                } else {
                    *reinterpret_cast<float2*>(outp + base) = make_float2(v0, v1);
                }
            }
        }
    }
}

// ---------------------------------------------------------------- launch
extern "C" void kernel_launch(void* const* d_in, const int* in_sizes, int n_in,
                              void* d_out, int out_size) {
    const float* x = (const float*)d_in[0];   // [8192, 1024]
    const float* W = (const float*)d_in[1];   // [1024, 4096]
    float* out = (float*)d_out;               // [8192, 1024]

    __half *xhi, *Whi, *Wthi, *ahi, *t1hi;
    cudaGetSymbolAddress((void**)&xhi,  g_xhi);
    cudaGetSymbolAddress((void**)&Whi,  g_Whi);
    cudaGetSymbolAddress((void**)&Wthi, g_Wthi);
    cudaGetSymbolAddress((void**)&ahi,  g_ahi);
    cudaGetSymbolAddress((void**)&t1hi, g_t1hi);

    cudaFuncSetAttribute((const void*)lca_gemm_big<0>,   cudaFuncAttributeMaxDynamicSharedMemorySize, SMEM_BIG);
    cudaFuncSetAttribute((const void*)lca_gemm_big<2>,   cudaFuncAttributeMaxDynamicSharedMemorySize, SMEM_BIG);
    cudaFuncSetAttribute((const void*)lca_gemm_small<1>, cudaFuncAttributeMaxDynamicSharedMemorySize, SMEM_SMALL);
    cudaFuncSetAttribute((const void*)lca_gemm_small<3>, cudaFuncAttributeMaxDynamicSharedMemorySize, SMEM_SMALL);

    // prep
    half_kernel<<<(int)(((size_t)NROWS * DMODEL) / 1024), 256>>>(x, xhi);
    half_kernel<<<(int)(((size_t)DMODEL * DLCA) / 1024), 256>>>(W, Whi);
    transpose_kernel<<<dim3(DLCA / 32, DMODEL / 32), dim3(32, 8)>>>(W);
    zero_diag_kernel<<<DLCA / 256, 256>>>();
    diag_kernel<<<dim3(DLCA / 512, 16), 512>>>();

    // b = fp16(x)@W~ ; u = 0.1b ; a = fp16(relu(u - lambda))
    lca_gemm_big<0><<<dim3(DLCA / 256, NROWS / 128), 512, SMEM_BIG>>>(
        xhi, Wthi, DMODEL);

    for (int it = 0; it < 9; ++it) {
        // t1 = a @ W~^T
        lca_gemm_small<1><<<dim3(DMODEL / 128, NROWS / 64), 256, SMEM_SMALL>>>(
            ahi, Whi, DLCA, nullptr);
        // u = 0.9u + 0.1(b - t1@W~ + a*diagG~) ; a = fp16(relu(u - lambda))
        lca_gemm_big<2><<<dim3(DLCA / 256, NROWS / 128), 512, SMEM_BIG>>>(
            t1hi, Wthi, DMODEL);
    }

    // out = a @ W~^T (fp32 out)
    lca_gemm_small<3><<<dim3(DMODEL / 128, NROWS / 64), 256, SMEM_SMALL>>>(
        ahi, Whi, DLCA, out);
}